// round 11
// baseline (speedup 1.0000x reference)
#include <cuda_runtime.h>

// Problem constants
#define NB   8
#define CCH  20
#define HH_  64
#define WW_  2048

// Tiling: each block does 10 channels x 4 rows x 128 cols
#define CC   10           // channels per block (chunk)
#define HT   4            // output rows per block
#define WT   128          // output cols per block
#define HT2  8            // HT + 4 halo rows
#define WVAL 132          // WT + 4 valid cols
#define WSTR 136          // padded row stride (floats): 544B, 16B-aligned rows

// smem layout (floats)
#define OFF_XYZ   0
#define OFF_MASK  (3 * HT2 * WSTR)                  // 3264
#define OFF_SM    (OFF_MASK + HT2 * WSTR)           // 4352
#define SMEM_FLOATS (OFF_SM + CC * HT2 * WSTR)      // 15232
#define SMEM_BYTES  (SMEM_FLOATS * 4)               // 60928

__global__ __launch_bounds__(128)
void lcxyz_kernel(const float* __restrict__ xyz,
                  const float* __restrict__ softmax,
                  const unsigned int* __restrict__ mask,  // int32 or f32 0/1: word!=0
                  float* __restrict__ out)
{
    extern __shared__ float smem[];
    float* s_xyz  = smem + OFF_XYZ;   // [3][HT2][WSTR]
    float* s_mask = smem + OFF_MASK;  // [HT2][WSTR]
    float* s_sm   = smem + OFF_SM;    // [CC][HT2][WSTR]

    const int tid  = threadIdx.x;
    const int wid  = tid >> 5;
    const int lane = tid & 31;

    const int n    = blockIdx.z >> 1;
    const int c0   = (blockIdx.z & 1) * CC;
    const int h0   = blockIdx.y * HT;
    const int w0   = blockIdx.x * WT;

    // ---- Phase 1a: xyz (torus wrap), 24 (ch,r) rows, one row per warp ----
    #pragma unroll 1
    for (int p = wid; p < 3 * HT2; p += 4) {
        const int ch = p >> 3;
        const int r  = p & 7;
        const int hh = (h0 + r - 2) & (HH_ - 1);
        const float* src = xyz + ((size_t)(n * 3 + ch) * HH_ + hh) * WW_;
        float* dst = s_xyz + p * WSTR;
        #pragma unroll
        for (int idx = lane; idx < WVAL; idx += 32) {
            int ww = (w0 + idx - 2) & (WW_ - 1);
            dst[idx] = src[ww];
        }
    }

    // ---- Phase 1b: mask (zero pad), 8 rows ----
    #pragma unroll 1
    for (int r = wid; r < HT2; r += 4) {
        const int hh = h0 + r - 2;
        const bool hv = (hh >= 0) && (hh < HH_);
        const unsigned int* src = mask + (size_t)(n * HH_ + hh) * WW_;
        float* dst = s_mask + r * WSTR;
        #pragma unroll
        for (int idx = lane; idx < WVAL; idx += 32) {
            int ww = w0 + idx - 2;
            float m = 0.0f;
            if (hv && (unsigned)ww < (unsigned)WW_)
                m = (src[ww] != 0u) ? 1.0f : 0.0f;
            dst[idx] = m;
        }
    }
    __syncthreads();

    // ---- Phase 2: masked softmax (zero pad), 80 (c,r) rows ----
    #pragma unroll 1
    for (int p = wid; p < CC * HT2; p += 4) {
        const int c = p >> 3;
        const int r = p & 7;
        const int hh = h0 + r - 2;
        const bool hv = (hh >= 0) && (hh < HH_);
        const float* src = softmax + ((size_t)(n * CCH + c0 + c) * HH_ + hh) * WW_;
        const float* mrow = s_mask + r * WSTR;
        float* dst = s_sm + p * WSTR;
        #pragma unroll
        for (int idx = lane; idx < WVAL; idx += 32) {
            int ww = w0 + idx - 2;
            float v = 0.0f;
            if (hv && (unsigned)ww < (unsigned)WW_)
                v = src[ww] * mrow[idx];
            dst[idx] = v;
        }
    }
    __syncthreads();

    // ---- Phase 3: compute. Thread (tx,ty): 4 outputs at (h0+ty, w0+4*tx..+3) ----
    const int tx = lane;
    const int ty = wid;
    const int wl = tx << 2;   // smem phys col of output o is wl+o+2

    // center xyz (row ty+2)
    float xc0[4], xc1[4], xc2[4];
    #pragma unroll
    for (int o = 0; o < 4; ++o) {
        xc0[o] = s_xyz[(0 * HT2 + ty + 2) * WSTR + wl + o + 2];
        xc1[o] = s_xyz[(1 * HT2 + ty + 2) * WSTR + wl + o + 2];
        xc2[o] = s_xyz[(2 * HT2 + ty + 2) * WSTR + wl + o + 2];
    }

    float acc[CC][4];
    #pragma unroll
    for (int c = 0; c < CC; ++c)
        #pragma unroll
        for (int o = 0; o < 4; ++o) acc[c][o] = 0.0f;

    #pragma unroll 1
    for (int di = 0; di < 5; ++di) {
        const int r = ty + di;

        // xyz window: phys cols wl..wl+7 (16B aligned), 3 channels
        float xv0[8], xv1[8], xv2[8];
        {
            const float4* p = (const float4*)&s_xyz[(0 * HT2 + r) * WSTR + wl];
            float4 a = p[0], b = p[1];
            xv0[0]=a.x; xv0[1]=a.y; xv0[2]=a.z; xv0[3]=a.w;
            xv0[4]=b.x; xv0[5]=b.y; xv0[6]=b.z; xv0[7]=b.w;
        }
        {
            const float4* p = (const float4*)&s_xyz[(1 * HT2 + r) * WSTR + wl];
            float4 a = p[0], b = p[1];
            xv1[0]=a.x; xv1[1]=a.y; xv1[2]=a.z; xv1[3]=a.w;
            xv1[4]=b.x; xv1[5]=b.y; xv1[6]=b.z; xv1[7]=b.w;
        }
        {
            const float4* p = (const float4*)&s_xyz[(2 * HT2 + r) * WSTR + wl];
            float4 a = p[0], b = p[1];
            xv2[0]=a.x; xv2[1]=a.y; xv2[2]=a.z; xv2[3]=a.w;
            xv2[4]=b.x; xv2[5]=b.y; xv2[6]=b.z; xv2[7]=b.w;
        }

        // 20 weights for this di: wgt[o][dj] = exp(-d2/2)
        float wgt[4][5];
        #pragma unroll
        for (int dj = 0; dj < 5; ++dj) {
            #pragma unroll
            for (int o = 0; o < 4; ++o) {
                float dx = xv0[o + dj] - xc0[o];
                float dy = xv1[o + dj] - xc1[o];
                float dz = xv2[o + dj] - xc2[o];
                float d2 = dx * dx + dy * dy + dz * dz;
                wgt[o][dj] = __expf(-0.5f * d2);
            }
        }

        // accumulate 10 channels: 2 x LDS.128 + 20 FFMA per channel
        #pragma unroll
        for (int c = 0; c < CC; ++c) {
            const float4* p = (const float4*)&s_sm[(c * HT2 + r) * WSTR + wl];
            float4 a = p[0], b = p[1];
            float s[8];
            s[0]=a.x; s[1]=a.y; s[2]=a.z; s[3]=a.w;
            s[4]=b.x; s[5]=b.y; s[6]=b.z; s[7]=b.w;
            #pragma unroll
            for (int o = 0; o < 4; ++o) {
                #pragma unroll
                for (int dj = 0; dj < 5; ++dj)
                    acc[c][o] += wgt[o][dj] * s[o + dj];
            }
        }
    }

    // ---- store: float4 per channel ----
    const int gh = h0 + ty;
    const int gw = w0 + wl;
    #pragma unroll
    for (int c = 0; c < CC; ++c) {
        float4 v = make_float4(acc[c][0], acc[c][1], acc[c][2], acc[c][3]);
        *(float4*)&out[((size_t)(n * CCH + c0 + c) * HH_ + gh) * WW_ + gw] = v;
    }
}

extern "C" void kernel_launch(void* const* d_in, const int* in_sizes, int n_in,
                              void* d_out, int out_size)
{
    const float*        xyz  = (const float*)d_in[0];
    const float*        sm   = (const float*)d_in[1];
    const unsigned int* mask = (const unsigned int*)d_in[2];
    float*              out  = (float*)d_out;

    (void)in_sizes; (void)n_in; (void)out_size;

    cudaFuncSetAttribute(lcxyz_kernel,
                         cudaFuncAttributeMaxDynamicSharedMemorySize,
                         SMEM_BYTES);

    dim3 grid(WW_ / WT, HH_ / HT, NB * 2);   // 16 x 16 x 16 = 4096 blocks
    lcxyz_kernel<<<grid, 128, SMEM_BYTES>>>(xyz, sm, mask, out);
}

// round 12
// speedup vs baseline: 1.5254x; 1.5254x over previous
#include <cuda_runtime.h>

// Problem constants
#define NB   8
#define CCH  20
#define HH_  64
#define WW_  2048
#define TOT  (NB * CCH * HH_ * WW_)   // 20,971,520 floats in softmax

// Tiling: each block: 10 channels x 4 rows x 128 cols
#define CC   10
#define HT   4
#define WT   128
#define HT2  8            // HT + 4 halo rows
#define WVAL 132          // WT + 4 valid cols
#define WSTR 136          // padded row stride (floats)

// smem: xyz tile + padded mask tile only (softmax read from global/L1)
#define OFF_XYZ   0
#define OFF_MASK  (3 * HT2 * WSTR)                 // 3264
#define SMEM_FLOATS (OFF_MASK + HT2 * WSTR)        // 4352
#define SMEM_BYTES  (SMEM_FLOATS * 4)              // 17408

__global__ __launch_bounds__(128)
void lcxyz_kernel(const float* __restrict__ xyz,
                  const float* __restrict__ softmax,
                  const unsigned int* __restrict__ mask,  // 4-byte 0/1: word!=0
                  float* __restrict__ out)
{
    extern __shared__ float smem[];
    float* s_xyz  = smem + OFF_XYZ;   // [3][HT2][WSTR]
    float* s_mask = smem + OFF_MASK;  // [HT2][WSTR]

    const int tid  = threadIdx.x;
    const int wid  = tid >> 5;
    const int lane = tid & 31;

    const int n    = blockIdx.z >> 1;
    const int c0   = (blockIdx.z & 1) * CC;
    const int h0   = blockIdx.y * HT;
    const int w0   = blockIdx.x * WT;

    // ---- stage xyz (torus wrap): 24 (ch,r) rows ----
    #pragma unroll 1
    for (int p = wid; p < 3 * HT2; p += 4) {
        const int ch = p >> 3;
        const int r  = p & 7;
        const int hh = (h0 + r - 2) & (HH_ - 1);
        const float* src = xyz + ((size_t)(n * 3 + ch) * HH_ + hh) * WW_;
        float* dst = s_xyz + p * WSTR;
        #pragma unroll
        for (int idx = lane; idx < WVAL; idx += 32) {
            int ww = (w0 + idx - 2) & (WW_ - 1);
            dst[idx] = src[ww];
        }
    }

    // ---- stage mask (zero pad outside frame): 8 rows ----
    #pragma unroll 1
    for (int r = wid; r < HT2; r += 4) {
        const int hh = h0 + r - 2;
        const bool hv = (hh >= 0) && (hh < HH_);
        const unsigned int* src = mask + (size_t)(n * HH_ + hh) * WW_;
        float* dst = s_mask + r * WSTR;
        #pragma unroll
        for (int idx = lane; idx < WVAL; idx += 32) {
            int ww = w0 + idx - 2;
            float m = 0.0f;
            if (hv && (unsigned)ww < (unsigned)WW_)
                m = (src[ww] != 0u) ? 1.0f : 0.0f;
            dst[idx] = m;
        }
    }
    __syncthreads();

    // ---- compute: thread (lane,wid) -> 4 outputs at (h0+wid, w0+4*lane..+3) ----
    const int ty = wid;
    const int wl = lane << 2;      // smem phys col of output o is wl+o+2
    const int gw = w0 + wl;        // global col of output 0

    // center xyz (row ty+2)
    float xc0[4], xc1[4], xc2[4];
    #pragma unroll
    for (int o = 0; o < 4; ++o) {
        xc0[o] = s_xyz[(0 * HT2 + ty + 2) * WSTR + wl + o + 2];
        xc1[o] = s_xyz[(1 * HT2 + ty + 2) * WSTR + wl + o + 2];
        xc2[o] = s_xyz[(2 * HT2 + ty + 2) * WSTR + wl + o + 2];
    }

    float acc[CC][4];
    #pragma unroll
    for (int c = 0; c < CC; ++c)
        #pragma unroll
        for (int o = 0; o < 4; ++o) acc[c][o] = 0.0f;

    #pragma unroll 1
    for (int di = 0; di < 5; ++di) {
        const int r = ty + di;

        // xyz window: phys cols wl..wl+7, 3 channels (6 x LDS.128)
        float xv0[8], xv1[8], xv2[8];
        {
            const float4* p = (const float4*)&s_xyz[(0 * HT2 + r) * WSTR + wl];
            float4 a = p[0], b = p[1];
            xv0[0]=a.x; xv0[1]=a.y; xv0[2]=a.z; xv0[3]=a.w;
            xv0[4]=b.x; xv0[5]=b.y; xv0[6]=b.z; xv0[7]=b.w;
        }
        {
            const float4* p = (const float4*)&s_xyz[(1 * HT2 + r) * WSTR + wl];
            float4 a = p[0], b = p[1];
            xv1[0]=a.x; xv1[1]=a.y; xv1[2]=a.z; xv1[3]=a.w;
            xv1[4]=b.x; xv1[5]=b.y; xv1[6]=b.z; xv1[7]=b.w;
        }
        {
            const float4* p = (const float4*)&s_xyz[(2 * HT2 + r) * WSTR + wl];
            float4 a = p[0], b = p[1];
            xv2[0]=a.x; xv2[1]=a.y; xv2[2]=a.z; xv2[3]=a.w;
            xv2[4]=b.x; xv2[5]=b.y; xv2[6]=b.z; xv2[7]=b.w;
        }

        // mask window for this source row (2 x LDS.128)
        float mv[8];
        {
            const float4* p = (const float4*)&s_mask[r * WSTR + wl];
            float4 a = p[0], b = p[1];
            mv[0]=a.x; mv[1]=a.y; mv[2]=a.z; mv[3]=a.w;
            mv[4]=b.x; mv[5]=b.y; mv[6]=b.z; mv[7]=b.w;
        }

        // 20 masked weights: wgt[o][dj] = exp(-d2/2) * mask(src)
        float wgt[4][5];
        #pragma unroll
        for (int dj = 0; dj < 5; ++dj) {
            #pragma unroll
            for (int o = 0; o < 4; ++o) {
                float dx = xv0[o + dj] - xc0[o];
                float dy = xv1[o + dj] - xc1[o];
                float dz = xv2[o + dj] - xc2[o];
                float d2 = dx * dx + dy * dy + dz * dz;
                wgt[o][dj] = __expf(-0.5f * d2) * mv[o + dj];
            }
        }

        // source row, clamped into frame (weights are 0 when out-of-frame)
        const int rg  = h0 + ty + di - 2;
        const int hcl = min(max(rg, 0), HH_ - 1);
        // aligned 12-float window base: cols gw-4 .. gw+7 (use slots 2..9)
        const int base0 = ((n * CCH + c0) * HH_ + hcl) * WW_ + gw - 4;

        // 10 channels: 3 x LDG.128 (L1-hot) + 20 FFMA each; MLP ~30
        #pragma unroll
        for (int c = 0; c < CC; ++c) {
            const int base = base0 + c * (HH_ * WW_);
            const int l0 = max(base, 0);            // left-edge clamp (mask-zero slots)
            const int l2 = min(base + 8, TOT - 4);  // buffer-end clamp (mask-zero slots)
            float4 a = *(const float4*)&softmax[l0];
            float4 b = *(const float4*)&softmax[base + 4];
            float4 d = *(const float4*)&softmax[l2];
            float s[12];
            s[0]=a.x; s[1]=a.y; s[2]=a.z;  s[3]=a.w;
            s[4]=b.x; s[5]=b.y; s[6]=b.z;  s[7]=b.w;
            s[8]=d.x; s[9]=d.y; s[10]=d.z; s[11]=d.w;
            #pragma unroll
            for (int o = 0; o < 4; ++o) {
                #pragma unroll
                for (int dj = 0; dj < 5; ++dj)
                    acc[c][o] += wgt[o][dj] * s[2 + o + dj];
            }
        }
    }

    // ---- store: float4 per channel ----
    const int gh = h0 + ty;
    #pragma unroll
    for (int c = 0; c < CC; ++c) {
        float4 v = make_float4(acc[c][0], acc[c][1], acc[c][2], acc[c][3]);
        *(float4*)&out[((size_t)(n * CCH + c0 + c) * HH_ + gh) * WW_ + gw] = v;
    }
}

extern "C" void kernel_launch(void* const* d_in, const int* in_sizes, int n_in,
                              void* d_out, int out_size)
{
    const float*        xyz  = (const float*)d_in[0];
    const float*        sm   = (const float*)d_in[1];
    const unsigned int* mask = (const unsigned int*)d_in[2];
    float*              out  = (float*)d_out;

    (void)in_sizes; (void)n_in; (void)out_size;

    dim3 grid(WW_ / WT, HH_ / HT, NB * 2);   // 16 x 16 x 16 = 4096 blocks
    lcxyz_kernel<<<grid, 128, SMEM_BYTES>>>(xyz, sm, mask, out);
}

// round 13
// speedup vs baseline: 1.6814x; 1.1022x over previous
#include <cuda_runtime.h>

// Problem constants
#define NB   8
#define CCH  20
#define HH_  64
#define WW_  2048
#define HW   (HH_ * WW_)
#define TOT  (NB * CCH * HW)

// Tiling: each block: 10 channels x 4 rows x 128 cols
#define CC   10
#define HT   4
#define WT   128
#define HT2  8            // HT + 4 halo rows
#define WVAL 132          // WT + 4 valid cols
#define WSTR 136          // padded row stride (floats)

// smem: poisoned xyz tile only
#define SMEM_FLOATS (3 * HT2 * WSTR)               // 3264
#define SMEM_BYTES  (SMEM_FLOATS * 4)              // 13056

#define POISON 1e18f

__global__ __launch_bounds__(128, 6)
void lcxyz_kernel(const float* __restrict__ xyz,
                  const float* __restrict__ softmax,
                  const unsigned int* __restrict__ mask,  // 4-byte 0/1: word!=0
                  float* __restrict__ out)
{
    extern __shared__ float smem[];
    float* s_xyz = smem;              // [3][HT2][WSTR], poisoned where masked/out-of-frame

    const int tid  = threadIdx.x;
    const int wid  = tid >> 5;
    const int lane = tid & 31;

    const int n    = blockIdx.z >> 1;
    const int c0   = (blockIdx.z & 1) * CC;
    const int h0   = blockIdx.y * HT;
    const int w0   = blockIdx.x * WT;

    // ---- stage xyz with poison masking: 8 rows, one per warp x2 ----
    // slot (r, idx) = source (h0+r-2, w0+idx-2). Out-of-frame or mask==0 -> POISON.
    #pragma unroll 1
    for (int r = wid; r < HT2; r += 4) {
        const int hh = h0 + r - 2;
        const bool hv = (hh >= 0) && (hh < HH_);
        const unsigned int* msrc = mask + (size_t)(n * HH_ + hh) * WW_;
        const float* x0 = xyz + ((size_t)(n * 3 + 0) * HH_ + hh) * WW_;
        const float* x1 = x0 + (size_t)HW;
        const float* x2 = x1 + (size_t)HW;
        float* d0 = s_xyz + (0 * HT2 + r) * WSTR;
        float* d1 = s_xyz + (1 * HT2 + r) * WSTR;
        float* d2 = s_xyz + (2 * HT2 + r) * WSTR;
        #pragma unroll
        for (int idx = lane; idx < WVAL; idx += 32) {
            const int ww = w0 + idx - 2;
            const bool ok = hv && ((unsigned)ww < (unsigned)WW_);
            if (ok && msrc[ww] != 0u) {
                d0[idx] = x0[ww];
                d1[idx] = x1[ww];
                d2[idx] = x2[ww];
            } else {
                d0[idx] = POISON;
                d1[idx] = POISON;
                d2[idx] = POISON;
            }
        }
    }

    // ---- center xyz from GLOBAL (always real, even if masked) ----
    const int ty = wid;
    const int wl = lane << 2;
    const int gw = w0 + wl;
    const int gh = h0 + ty;

    float xc0[4], xc1[4], xc2[4];
    {
        const size_t cb = ((size_t)(n * 3) * HH_ + gh) * WW_ + gw;
        float4 a = *(const float4*)&xyz[cb];
        float4 b = *(const float4*)&xyz[cb + HW];
        float4 c = *(const float4*)&xyz[cb + 2 * (size_t)HW];
        xc0[0]=a.x; xc0[1]=a.y; xc0[2]=a.z; xc0[3]=a.w;
        xc1[0]=b.x; xc1[1]=b.y; xc1[2]=b.z; xc1[3]=b.w;
        xc2[0]=c.x; xc2[1]=c.y; xc2[2]=c.z; xc2[3]=c.w;
    }

    float acc[CC][4];
    #pragma unroll
    for (int c = 0; c < CC; ++c)
        #pragma unroll
        for (int o = 0; o < 4; ++o) acc[c][o] = 0.0f;

    __syncthreads();

    #pragma unroll 1
    for (int di = 0; di < 5; ++di) {
        const int r = ty + di;

        // xyz window: phys cols wl..wl+7, 3 channels (6 x LDS.128)
        float xv0[8], xv1[8], xv2[8];
        {
            const float4* p = (const float4*)&s_xyz[(0 * HT2 + r) * WSTR + wl];
            float4 a = p[0], b = p[1];
            xv0[0]=a.x; xv0[1]=a.y; xv0[2]=a.z; xv0[3]=a.w;
            xv0[4]=b.x; xv0[5]=b.y; xv0[6]=b.z; xv0[7]=b.w;
        }
        {
            const float4* p = (const float4*)&s_xyz[(1 * HT2 + r) * WSTR + wl];
            float4 a = p[0], b = p[1];
            xv1[0]=a.x; xv1[1]=a.y; xv1[2]=a.z; xv1[3]=a.w;
            xv1[4]=b.x; xv1[5]=b.y; xv1[6]=b.z; xv1[7]=b.w;
        }
        {
            const float4* p = (const float4*)&s_xyz[(2 * HT2 + r) * WSTR + wl];
            float4 a = p[0], b = p[1];
            xv2[0]=a.x; xv2[1]=a.y; xv2[2]=a.z; xv2[3]=a.w;
            xv2[4]=b.x; xv2[5]=b.y; xv2[6]=b.z; xv2[7]=b.w;
        }

        // 20 weights: exp(-d2/2); poisoned sources give exactly 0
        float wgt[4][5];
        #pragma unroll
        for (int dj = 0; dj < 5; ++dj) {
            #pragma unroll
            for (int o = 0; o < 4; ++o) {
                float dx = xv0[o + dj] - xc0[o];
                float dy = xv1[o + dj] - xc1[o];
                float dz = xv2[o + dj] - xc2[o];
                float d2 = dx * dx + dy * dy + dz * dz;
                wgt[o][dj] = __expf(-0.5f * d2);
            }
        }

        // source row clamped into frame (out-of-frame taps have wgt==0)
        const int rg  = gh + di - 2;
        const int hcl = min(max(rg, 0), HH_ - 1);
        const int base0 = ((n * CCH + c0) * HH_ + hcl) * WW_ + gw - 4;

        // 10 channels: 3 x LDG.128 + 20 FFMA each (clamps only on end channels)
        #pragma unroll
        for (int c = 0; c < CC; ++c) {
            const int base = base0 + c * HW;
            int i0 = base;
            int i2 = base + 8;
            if (c == 0)      i0 = max(i0, 0);        // only c==0 can underflow
            if (c == CC - 1) i2 = min(i2, TOT - 4);  // only last can overflow
            float4 a = *(const float4*)&softmax[i0];
            float4 b = *(const float4*)&softmax[base + 4];
            float4 d = *(const float4*)&softmax[i2];
            float s[12];
            s[0]=a.x; s[1]=a.y; s[2]=a.z;  s[3]=a.w;
            s[4]=b.x; s[5]=b.y; s[6]=b.z;  s[7]=b.w;
            s[8]=d.x; s[9]=d.y; s[10]=d.z; s[11]=d.w;
            #pragma unroll
            for (int o = 0; o < 4; ++o) {
                #pragma unroll
                for (int dj = 0; dj < 5; ++dj)
                    acc[c][o] += wgt[o][dj] * s[2 + o + dj];
            }
        }
    }

    // ---- store: float4 per channel ----
    #pragma unroll
    for (int c = 0; c < CC; ++c) {
        float4 v = make_float4(acc[c][0], acc[c][1], acc[c][2], acc[c][3]);
        *(float4*)&out[((size_t)(n * CCH + c0 + c) * HH_ + gh) * WW_ + gw] = v;
    }
}

extern "C" void kernel_launch(void* const* d_in, const int* in_sizes, int n_in,
                              void* d_out, int out_size)
{
    const float*        xyz  = (const float*)d_in[0];
    const float*        sm   = (const float*)d_in[1];
    const unsigned int* mask = (const unsigned int*)d_in[2];
    float*              out  = (float*)d_out;

    (void)in_sizes; (void)n_in; (void)out_size;

    dim3 grid(WW_ / WT, HH_ / HT, NB * 2);   // 16 x 16 x 16 = 4096 blocks
    lcxyz_kernel<<<grid, 128, SMEM_BYTES>>>(xyz, sm, mask, out);
}

// round 14
// speedup vs baseline: 1.6986x; 1.0102x over previous
#include <cuda_runtime.h>

// Problem constants
#define NB   8
#define CCH  20
#define HH_  64
#define WW_  2048
#define HW   (HH_ * WW_)
#define TOT  (NB * CCH * HW)

// Tiling: each block: 10 channels x 4 rows x 128 cols
#define CC   10
#define HT   4
#define WT   128
#define HT2  8            // HT + 4 halo rows
#define WVAL 132          // WT + 4 valid cols
#define WSTR 136          // padded row stride (floats)

// smem: poisoned xyz tile only
#define SMEM_FLOATS (3 * HT2 * WSTR)               // 3264
#define SMEM_BYTES  (SMEM_FLOATS * 4)              // 13056

#define POISON 1e18f

__global__ __launch_bounds__(128, 6)
void lcxyz_kernel(const float* __restrict__ xyz,
                  const float* __restrict__ softmax,
                  const unsigned int* __restrict__ mask,  // 4-byte 0/1: word!=0
                  float* __restrict__ out)
{
    extern __shared__ float smem[];
    float* s_xyz = smem;              // [3][HT2][WSTR], poisoned where masked/out-of-frame

    const int tid  = threadIdx.x;
    const int wid  = tid >> 5;
    const int lane = tid & 31;

    const int n    = blockIdx.z >> 1;
    const int c0   = (blockIdx.z & 1) * CC;
    const int h0   = blockIdx.y * HT;
    const int w0   = blockIdx.x * WT;

    // ---- stage xyz with poison masking: 8 rows, one per warp x2 ----
    // slot (r, idx) = source (h0+r-2, w0+idx-2). Out-of-frame or mask==0 -> POISON.
    #pragma unroll 1
    for (int r = wid; r < HT2; r += 4) {
        const int hh = h0 + r - 2;
        const bool hv = (hh >= 0) && (hh < HH_);
        const unsigned int* msrc = mask + (size_t)(n * HH_ + hh) * WW_;
        const float* x0 = xyz + ((size_t)(n * 3 + 0) * HH_ + hh) * WW_;
        const float* x1 = x0 + (size_t)HW;
        const float* x2 = x1 + (size_t)HW;
        float* d0 = s_xyz + (0 * HT2 + r) * WSTR;
        float* d1 = s_xyz + (1 * HT2 + r) * WSTR;
        float* d2 = s_xyz + (2 * HT2 + r) * WSTR;
        #pragma unroll
        for (int idx = lane; idx < WVAL; idx += 32) {
            const int ww = w0 + idx - 2;
            const bool ok = hv && ((unsigned)ww < (unsigned)WW_);
            if (ok && msrc[ww] != 0u) {
                d0[idx] = x0[ww];
                d1[idx] = x1[ww];
                d2[idx] = x2[ww];
            } else {
                d0[idx] = POISON;
                d1[idx] = POISON;
                d2[idx] = POISON;
            }
        }
    }

    // ---- center xyz from GLOBAL (always real, even if masked) ----
    const int ty = wid;
    const int wl = lane << 2;
    const int gw = w0 + wl;
    const int gh = h0 + ty;

    float xc0[4], xc1[4], xc2[4];
    {
        const size_t cb = ((size_t)(n * 3) * HH_ + gh) * WW_ + gw;
        float4 a = *(const float4*)&xyz[cb];
        float4 b = *(const float4*)&xyz[cb + HW];
        float4 c = *(const float4*)&xyz[cb + 2 * (size_t)HW];
        xc0[0]=a.x; xc0[1]=a.y; xc0[2]=a.z; xc0[3]=a.w;
        xc1[0]=b.x; xc1[1]=b.y; xc1[2]=b.z; xc1[3]=b.w;
        xc2[0]=c.x; xc2[1]=c.y; xc2[2]=c.z; xc2[3]=c.w;
    }

    float acc[CC][4];
    #pragma unroll
    for (int c = 0; c < CC; ++c)
        #pragma unroll
        for (int o = 0; o < 4; ++o) acc[c][o] = 0.0f;

    __syncthreads();

    #pragma unroll 1
    for (int di = 0; di < 5; ++di) {
        const int r = ty + di;

        // xyz window: phys cols wl..wl+7, 3 channels (6 x LDS.128)
        float xv0[8], xv1[8], xv2[8];
        {
            const float4* p = (const float4*)&s_xyz[(0 * HT2 + r) * WSTR + wl];
            float4 a = p[0], b = p[1];
            xv0[0]=a.x; xv0[1]=a.y; xv0[2]=a.z; xv0[3]=a.w;
            xv0[4]=b.x; xv0[5]=b.y; xv0[6]=b.z; xv0[7]=b.w;
        }
        {
            const float4* p = (const float4*)&s_xyz[(1 * HT2 + r) * WSTR + wl];
            float4 a = p[0], b = p[1];
            xv1[0]=a.x; xv1[1]=a.y; xv1[2]=a.z; xv1[3]=a.w;
            xv1[4]=b.x; xv1[5]=b.y; xv1[6]=b.z; xv1[7]=b.w;
        }
        {
            const float4* p = (const float4*)&s_xyz[(2 * HT2 + r) * WSTR + wl];
            float4 a = p[0], b = p[1];
            xv2[0]=a.x; xv2[1]=a.y; xv2[2]=a.z; xv2[3]=a.w;
            xv2[4]=b.x; xv2[5]=b.y; xv2[6]=b.z; xv2[7]=b.w;
        }

        // 20 weights: exp(-d2/2); poisoned sources give exactly 0
        float wgt[4][5];
        #pragma unroll
        for (int dj = 0; dj < 5; ++dj) {
            #pragma unroll
            for (int o = 0; o < 4; ++o) {
                float dx = xv0[o + dj] - xc0[o];
                float dy = xv1[o + dj] - xc1[o];
                float dz = xv2[o + dj] - xc2[o];
                float d2 = dx * dx + dy * dy + dz * dz;
                wgt[o][dj] = __expf(-0.5f * d2);
            }
        }

        // source row clamped into frame (out-of-frame taps have wgt==0)
        const int rg  = gh + di - 2;
        const int hcl = min(max(rg, 0), HH_ - 1);
        const int base0 = ((n * CCH + c0) * HH_ + hcl) * WW_ + gw - 4;

        // 10 channels: 3 x LDG.128 + 20 FFMA each (clamps only on end channels)
        #pragma unroll
        for (int c = 0; c < CC; ++c) {
            const int base = base0 + c * HW;
            int i0 = base;
            int i2 = base + 8;
            if (c == 0)      i0 = max(i0, 0);        // only c==0 can underflow
            if (c == CC - 1) i2 = min(i2, TOT - 4);  // only last can overflow
            float4 a = *(const float4*)&softmax[i0];
            float4 b = *(const float4*)&softmax[base + 4];
            float4 d = *(const float4*)&softmax[i2];
            float s[12];
            s[0]=a.x; s[1]=a.y; s[2]=a.z;  s[3]=a.w;
            s[4]=b.x; s[5]=b.y; s[6]=b.z;  s[7]=b.w;
            s[8]=d.x; s[9]=d.y; s[10]=d.z; s[11]=d.w;
            #pragma unroll
            for (int o = 0; o < 4; ++o) {
                #pragma unroll
                for (int dj = 0; dj < 5; ++dj)
                    acc[c][o] += wgt[o][dj] * s[2 + o + dj];
            }
        }
    }

    // ---- store: float4 per channel ----
    #pragma unroll
    for (int c = 0; c < CC; ++c) {
        float4 v = make_float4(acc[c][0], acc[c][1], acc[c][2], acc[c][3]);
        *(float4*)&out[((size_t)(n * CCH + c0 + c) * HH_ + gh) * WW_ + gw] = v;
    }
}

extern "C" void kernel_launch(void* const* d_in, const int* in_sizes, int n_in,
                              void* d_out, int out_size)
{
    const float*        xyz  = (const float*)d_in[0];
    const float*        sm   = (const float*)d_in[1];
    const unsigned int* mask = (const unsigned int*)d_in[2];
    float*              out  = (float*)d_out;

    (void)in_sizes; (void)n_in; (void)out_size;

    dim3 grid(WW_ / WT, HH_ / HT, NB * 2);   // 16 x 16 x 16 = 4096 blocks
    lcxyz_kernel<<<grid, 128, SMEM_BYTES>>>(xyz, sm, mask, out);
}